// round 1
// baseline (speedup 1.0000x reference)
#include <cuda_runtime.h>

#define NZ 32
#define NY 1024
#define NX 1024
#define DXI (1.0f / 1000.0f)
#define DYI (1.0f / 1000.0f)
#define WENO_EPS 1e-6f

#define BX 32
#define BY 8

// Single-reciprocal WENO5 reconstruction (Jiang-Shu).
// result = (w0*p0 + w1*p1 + w2*p2) / (w0 + w1 + w2) with
// w_i = c_i * prod_{j!=i} (eps + b_j)^2  -- same ratio as c_i/(eps+b_i)^2 weights.
__device__ __forceinline__ float weno5(float qm2, float qm1, float q0,
                                       float qp1, float qp2) {
    const float c1312 = 13.0f / 12.0f;
    float t0 = qm2 - 2.0f * qm1 + q0;
    float s0 = qm2 - 4.0f * qm1 + 3.0f * q0;
    float b0 = c1312 * t0 * t0 + 0.25f * s0 * s0;
    float t1 = qm1 - 2.0f * q0 + qp1;
    float s1 = qm1 - qp1;
    float b1 = c1312 * t1 * t1 + 0.25f * s1 * s1;
    float t2 = q0 - 2.0f * qp1 + qp2;
    float s2 = 3.0f * q0 - 4.0f * qp1 + qp2;
    float b2 = c1312 * t2 * t2 + 0.25f * s2 * s2;

    float d0 = WENO_EPS + b0; d0 *= d0;
    float d1 = WENO_EPS + b1; d1 *= d1;
    float d2 = WENO_EPS + b2; d2 *= d2;

    float w0 = 0.1f * (d1 * d2);
    float w1 = 0.6f * (d0 * d2);
    float w2 = 0.3f * (d0 * d1);

    const float i6 = 1.0f / 6.0f;
    float p0 = (2.0f * qm2 - 7.0f * qm1 + 11.0f * q0) * i6;
    float p1 = (-qm1 + 5.0f * q0 + 2.0f * qp1) * i6;
    float p2 = (2.0f * q0 + 5.0f * qp1 - qp2) * i6;

    float num = w0 * p0 + w1 * p1 + w2 * p2;
    float den = w0 + w1 + w2;
    return __fdividef(num, den);
}

// Upwinded flux at face f: stencil q[f-2..f+3], velocity vel at f.
// Select the 5 operands by upwind direction, then reconstruct ONCE.
__device__ __forceinline__ float weno_flux(float qm2, float qm1, float q0,
                                           float qp1, float qp2, float qp3,
                                           float vel) {
    bool pos = (vel >= 0.0f);
    float a = pos ? qm2 : qp3;
    float b = pos ? qm1 : qp2;
    float c = pos ? q0  : qp1;
    float d = pos ? qp1 : q0;
    float e = pos ? qp2 : qm1;
    return vel * weno5(a, b, c, d, e);
}

__global__ __launch_bounds__(BX * BY)
void adv3d_kernel(const float* __restrict__ h,
                  const float* __restrict__ u,
                  const float* __restrict__ v,
                  float* __restrict__ out) {
    const int k  = blockIdx.z;
    const int i0 = blockIdx.x * BX;
    const int j0 = blockIdx.y * BY;
    const int tx = threadIdx.x;
    const int ty = threadIdx.y;
    const int i  = i0 + tx;
    const int j  = j0 + ty;
    const int base = k * (NY * NX);

    // z boundary slabs: zero fill only (out buffer is poisoned).
    if (k == 0 || k == NZ - 1) {
        out[base + j * NX + i] = 0.0f;
        return;
    }

    __shared__ float sh[BY + 6][BX + 6];   // h tile: y in [j0-3, j0+BY+2], x in [i0-3, i0+BX+2]
    __shared__ float sfe[BY][BX + 1];      // east-face fluxes: sfe[ty][tx+1] = face at i; [ty][0] = face at i0-1
    __shared__ float sfn[BY + 1][BX];      // north-face fluxes: sfn[ty+1][tx] = face at j; [0][tx] = face at j0-1

    // Cooperative clamped tile load (clamping reproduces edge-pad semantics).
    const int tid = ty * BX + tx;
    #pragma unroll
    for (int idx = tid; idx < (BY + 6) * (BX + 6); idx += BX * BY) {
        int yy = idx / (BX + 6);
        int xx = idx - yy * (BX + 6);
        int gj = min(max(j0 - 3 + yy, 0), NY - 1);
        int gi = min(max(i0 - 3 + xx, 0), NX - 1);
        sh[yy][xx] = h[base + gj * NX + gi];
    }
    __syncthreads();

    // --- East (x) face at this thread's own i: stencil h[j][i-2..i+3] ---
    {
        float vel = __ldg(&u[base + j * NX + i]);
        const float* row = &sh[ty + 3][tx + 1];
        sfe[ty][tx + 1] = weno_flux(row[0], row[1], row[2], row[3], row[4], row[5], vel);
        if (tx == 0) {
            // halo face at i0-1 (only meaningful when i0 >= 1; unused otherwise)
            int fi = max(i0 - 1, 0);
            float vel2 = __ldg(&u[base + j * NX + fi]);
            const float* r2 = &sh[ty + 3][0];
            sfe[ty][0] = weno_flux(r2[0], r2[1], r2[2], r2[3], r2[4], r2[5], vel2);
        }
    }

    // --- North (y) face at this thread's own j: stencil h[j-2..j+3][i] ---
    {
        float vel = __ldg(&v[base + j * NX + i]);
        sfn[ty + 1][tx] = weno_flux(sh[ty + 1][tx + 3], sh[ty + 2][tx + 3],
                                    sh[ty + 3][tx + 3], sh[ty + 4][tx + 3],
                                    sh[ty + 5][tx + 3], sh[ty + 6][tx + 3], vel);
        if (ty == 0) {
            int fj = max(j0 - 1, 0);
            float vel2 = __ldg(&v[base + fj * NX + i]);
            sfn[0][tx] = weno_flux(sh[0][tx + 3], sh[1][tx + 3], sh[2][tx + 3],
                                   sh[3][tx + 3], sh[4][tx + 3], sh[5][tx + 3], vel2);
        }
    }
    __syncthreads();

    float val = 0.0f;
    if (j >= 2 && j <= NY - 3 && i >= 2 && i <= NX - 3) {
        float divx = (sfe[ty][tx + 1] - sfe[ty][tx]) * DXI;
        float divy = (sfn[ty + 1][tx] - sfn[ty][tx]) * DYI;
        val = -(divx + divy);
    }
    out[base + j * NX + i] = val;
}

extern "C" void kernel_launch(void* const* d_in, const int* in_sizes, int n_in,
                              void* d_out, int out_size) {
    const float* h = (const float*)d_in[0];
    const float* u = (const float*)d_in[1];
    const float* v = (const float*)d_in[2];
    float* out = (float*)d_out;

    dim3 block(BX, BY, 1);
    dim3 grid(NX / BX, NY / BY, NZ);
    adv3d_kernel<<<grid, block>>>(h, u, v, out);
}

// round 2
// speedup vs baseline: 1.1768x; 1.1768x over previous
#include <cuda_runtime.h>

#define NZ 32
#define NY 1024
#define NX 1024
#define SX (1.0f / (1000.0f * 6.0f))   // DXI / 6  (fluxes carry a uniform x6 factor)
#define SY (1.0f / (1000.0f * 6.0f))   // DYI / 6

#define BX 32
#define BY 8

typedef unsigned long long u64_t;

// ---- packed f32x2 primitives (sm_103a FFMA2 path) ----
__device__ __forceinline__ u64_t pk2(float lo, float hi) {
    u64_t r; asm("mov.b64 %0, {%1, %2};" : "=l"(r) : "f"(lo), "f"(hi)); return r;
}
__device__ __forceinline__ void upk2(u64_t p, float& lo, float& hi) {
    asm("mov.b64 {%0, %1}, %2;" : "=f"(lo), "=f"(hi) : "l"(p));
}
__device__ __forceinline__ u64_t f2add(u64_t a, u64_t b) {
    u64_t r; asm("add.rn.f32x2 %0, %1, %2;" : "=l"(r) : "l"(a), "l"(b)); return r;
}
__device__ __forceinline__ u64_t f2mul(u64_t a, u64_t b) {
    u64_t r; asm("mul.rn.f32x2 %0, %1, %2;" : "=l"(r) : "l"(a), "l"(b)); return r;
}
__device__ __forceinline__ u64_t f2fma(u64_t a, u64_t b, u64_t c) {
    u64_t r; asm("fma.rn.f32x2 %0, %1, %2, %3;" : "=l"(r) : "l"(a), "l"(b), "l"(c)); return r;
}
__device__ __forceinline__ u64_t bcast2(float x) {
    unsigned u = __float_as_uint(x);           // constant-folds for literals
    return ((u64_t)u << 32) | (u64_t)u;
}

// Packed WENO5 (Jiang-Shu), rescaled: B=12b, weights x10, polys x6.
// Returns reconstruction x6 for both lanes; the 1/6 is folded into SX/SY.
__device__ __forceinline__ void weno5x2(u64_t qm2, u64_t qm1, u64_t q0,
                                        u64_t qp1, u64_t qp2,
                                        float& r0, float& r1) {
    const u64_t cm2 = bcast2(-2.f), cm4 = bcast2(-4.f), c3 = bcast2(3.f),
                c13 = bcast2(13.f), cm1 = bcast2(-1.f), c6 = bcast2(6.f),
                c2  = bcast2(2.f),  cm7 = bcast2(-7.f), c11 = bcast2(11.f),
                c5  = bcast2(5.f),  cE  = bcast2(1.2e-5f);   // 12*eps

    u64_t t0 = f2add(f2fma(qm1, cm2, q0), qm2);              // qm2-2qm1+q0
    u64_t s0 = f2fma(qm1, cm4, f2fma(q0, c3, qm2));          // qm2-4qm1+3q0
    u64_t B0 = f2fma(f2mul(t0, c13), t0, f2mul(f2mul(s0, s0), c3));
    u64_t t1 = f2add(f2fma(q0, cm2, qp1), qm1);
    u64_t s1 = f2fma(qp1, cm1, qm1);                         // qm1-qp1
    u64_t B1 = f2fma(f2mul(t1, c13), t1, f2mul(f2mul(s1, s1), c3));
    u64_t t2 = f2add(f2fma(qp1, cm2, qp2), q0);
    u64_t s2 = f2fma(qp1, cm4, f2fma(q0, c3, qp2));          // 3q0-4qp1+qp2
    u64_t B2 = f2fma(f2mul(t2, c13), t2, f2mul(f2mul(s2, s2), c3));

    u64_t d0 = f2add(B0, cE); d0 = f2mul(d0, d0);
    u64_t d1 = f2add(B1, cE); d1 = f2mul(d1, d1);
    u64_t d2 = f2add(B2, cE); d2 = f2mul(d2, d2);

    u64_t w0 = f2mul(d1, d2);                                // x1
    u64_t w1 = f2mul(f2mul(d0, d2), c6);                     // x6
    u64_t w2 = f2mul(f2mul(d0, d1), c3);                     // x3

    u64_t P0 = f2fma(qm2, c2, f2fma(qm1, cm7, f2mul(q0, c11)));
    u64_t P1 = f2fma(qm1, cm1, f2fma(q0, c5, f2mul(qp1, c2)));
    u64_t P2 = f2fma(q0, c2, f2fma(qp1, c5, f2mul(qp2, cm1)));

    u64_t num = f2fma(w0, P0, f2fma(w1, P1, f2mul(w2, P2)));
    u64_t den = f2add(w0, f2add(w1, w2));
    float n0, n1, e0, e1;
    upk2(num, n0, n1); upk2(den, e0, e1);
    r0 = __fdividef(n0, e0);
    r1 = __fdividef(n1, e1);
}

// Scalar variant (same x6 scaling) for the lone x-halo face.
__device__ __forceinline__ float weno5s(float qm2, float qm1, float q0,
                                        float qp1, float qp2) {
    float t0 = qm2 - 2.f * qm1 + q0, s0 = qm2 - 4.f * qm1 + 3.f * q0;
    float B0 = 13.f * t0 * t0 + 3.f * s0 * s0;
    float t1 = qm1 - 2.f * q0 + qp1, s1 = qm1 - qp1;
    float B1 = 13.f * t1 * t1 + 3.f * s1 * s1;
    float t2 = q0 - 2.f * qp1 + qp2, s2 = 3.f * q0 - 4.f * qp1 + qp2;
    float B2 = 13.f * t2 * t2 + 3.f * s2 * s2;
    float d0 = 1.2e-5f + B0; d0 *= d0;
    float d1 = 1.2e-5f + B1; d1 *= d1;
    float d2 = 1.2e-5f + B2; d2 *= d2;
    float w0 = d1 * d2, w1 = 6.f * (d0 * d2), w2 = 3.f * (d0 * d1);
    float P0 = 2.f * qm2 - 7.f * qm1 + 11.f * q0;
    float P1 = -qm1 + 5.f * q0 + 2.f * qp1;
    float P2 = 2.f * q0 + 5.f * qp1 - qp2;
    return __fdividef(w0 * P0 + w1 * P1 + w2 * P2, w0 + w1 + w2);
}

__global__ __launch_bounds__(BX * BY)
void adv3d_kernel(const float* __restrict__ h,
                  const float* __restrict__ u,
                  const float* __restrict__ v,
                  float* __restrict__ out) {
    const int k  = blockIdx.z;
    const int i0 = blockIdx.x * 64;          // 64 output columns per block (2/thread)
    const int j0 = blockIdx.y * BY;
    const int tx = threadIdx.x, ty = threadIdx.y;
    const int ip = i0 + 2 * tx;              // first of this thread's two x-points
    const int j  = j0 + ty;
    const int base = k * (NY * NX);

    if (k == 0 || k == NZ - 1) {             // z boundary slabs: zeros
        *(float2*)&out[base + j * NX + ip] = make_float2(0.f, 0.f);
        return;
    }

    __shared__ __align__(16) float sh[14][72];      // h tile: j0-3..j0+10, i0-4..i0+67
    __shared__ __align__(16) float sfn[BY + 1][64]; // north-face fluxes rows j0-1..j0+7

    // Cooperative clamped tile load (clamp == edge-pad semantics).
    const int tid = ty * BX + tx;
    for (int idx = tid; idx < 14 * 72; idx += BX * BY) {
        int yy = idx / 72, xx = idx - yy * 72;
        int gj = min(max(j0 - 3 + yy, 0), NY - 1);
        int gi = min(max(i0 - 4 + xx, 0), NX - 1);
        sh[yy][xx] = h[base + gj * NX + gi];
    }
    __syncthreads();

    u64_t m2, m1, z0, p1, p2;

    // ---- east (x) faces at ip and ip+1 (one packed eval) ----
    float qx[8];
    {
        const float2* row = (const float2*)&sh[ty + 3][2 * tx + 2]; // global i: ip-2..ip+5
        float2 a = row[0], b = row[1], c = row[2], d = row[3];
        qx[0] = a.x; qx[1] = a.y; qx[2] = b.x; qx[3] = b.y;
        qx[4] = c.x; qx[5] = c.y; qx[6] = d.x; qx[7] = d.y;
    }
    float2 uv = *(const float2*)&u[base + j * NX + ip];
    {
        bool g0 = uv.x >= 0.f, g1 = uv.y >= 0.f;
        m2 = pk2(g0 ? qx[0] : qx[5], g1 ? qx[1] : qx[6]);
        m1 = pk2(g0 ? qx[1] : qx[4], g1 ? qx[2] : qx[5]);
        z0 = pk2(g0 ? qx[2] : qx[3], g1 ? qx[3] : qx[4]);
        p1 = pk2(g0 ? qx[3] : qx[2], g1 ? qx[4] : qx[3]);
        p2 = pk2(g0 ? qx[4] : qx[1], g1 ? qx[5] : qx[2]);
    }
    float fx0, fx1;
    weno5x2(m2, m1, z0, p1, p2, fx0, fx1);
    fx0 *= uv.x; fx1 *= uv.y;

    // face at ip-1 comes from the left neighbor's fx1 via shuffle; lane 0 computes it.
    float fx_m1 = __shfl_up_sync(0xffffffffu, fx1, 1);
    if (tx == 0) {
        float vel = __ldg(&u[base + j * NX + max(i0 - 1, 0)]);
        const float* r = &sh[ty + 3][1];     // global i0-3..i0+2
        bool g = vel >= 0.f;
        fx_m1 = vel * weno5s(g ? r[0] : r[5], g ? r[1] : r[4], g ? r[2] : r[3],
                             g ? r[3] : r[2], g ? r[4] : r[1]);
    }

    // ---- north (y) faces at row j, columns ip and ip+1 (one packed eval) ----
    float2 r6[6];
    #pragma unroll
    for (int m = 0; m < 6; m++)
        r6[m] = *(const float2*)&sh[ty + 1 + m][2 * tx + 4];   // global j-2..j+3
    float2 vv = *(const float2*)&v[base + j * NX + ip];
    {
        bool g0 = vv.x >= 0.f, g1 = vv.y >= 0.f;
        m2 = pk2(g0 ? r6[0].x : r6[5].x, g1 ? r6[0].y : r6[5].y);
        m1 = pk2(g0 ? r6[1].x : r6[4].x, g1 ? r6[1].y : r6[4].y);
        z0 = pk2(g0 ? r6[2].x : r6[3].x, g1 ? r6[2].y : r6[3].y);
        p1 = pk2(g0 ? r6[3].x : r6[2].x, g1 ? r6[3].y : r6[2].y);
        p2 = pk2(g0 ? r6[4].x : r6[1].x, g1 ? r6[4].y : r6[1].y);
    }
    float fy0, fy1;
    weno5x2(m2, m1, z0, p1, p2, fy0, fy1);
    fy0 *= vv.x; fy1 *= vv.y;
    *(float2*)&sfn[ty + 1][2 * tx] = make_float2(fy0, fy1);

    if (ty == 0) {   // halo row j0-1 (whole warp 0, uniform — no divergence)
        float2 rh[6];
        #pragma unroll
        for (int m = 0; m < 6; m++)
            rh[m] = *(const float2*)&sh[m][2 * tx + 4];        // global j0-3..j0+2
        float2 vh = *(const float2*)&v[base + max(j0 - 1, 0) * NX + ip];
        bool g0 = vh.x >= 0.f, g1 = vh.y >= 0.f;
        m2 = pk2(g0 ? rh[0].x : rh[5].x, g1 ? rh[0].y : rh[5].y);
        m1 = pk2(g0 ? rh[1].x : rh[4].x, g1 ? rh[1].y : rh[4].y);
        z0 = pk2(g0 ? rh[2].x : rh[3].x, g1 ? rh[2].y : rh[3].y);
        p1 = pk2(g0 ? rh[3].x : rh[2].x, g1 ? rh[3].y : rh[2].y);
        p2 = pk2(g0 ? rh[4].x : rh[1].x, g1 ? rh[4].y : rh[1].y);
        float fh0, fh1;
        weno5x2(m2, m1, z0, p1, p2, fh0, fh1);
        *(float2*)&sfn[0][2 * tx] = make_float2(fh0 * vh.x, fh1 * vh.y);
    }
    __syncthreads();

    float2 fnp = *(const float2*)&sfn[ty][2 * tx];   // north face at row j-1

    float o0 = 0.f, o1 = 0.f;
    if (j >= 2 && j <= NY - 3) {
        if (ip >= 2 && ip <= NX - 3)
            o0 = -((fx0 - fx_m1) * SX + (fy0 - fnp.x) * SY);
        if (ip + 1 >= 2 && ip + 1 <= NX - 3)
            o1 = -((fx1 - fx0) * SX + (fy1 - fnp.y) * SY);
    }
    *(float2*)&out[base + j * NX + ip] = make_float2(o0, o1);
}

extern "C" void kernel_launch(void* const* d_in, const int* in_sizes, int n_in,
                              void* d_out, int out_size) {
    const float* h = (const float*)d_in[0];
    const float* u = (const float*)d_in[1];
    const float* v = (const float*)d_in[2];
    float* out = (float*)d_out;

    dim3 block(BX, BY, 1);
    dim3 grid(NX / 64, NY / BY, NZ);
    adv3d_kernel<<<grid, block>>>(h, u, v, out);
}

// round 3
// speedup vs baseline: 1.5850x; 1.3468x over previous
#include <cuda_runtime.h>

#define NZ 32
#define NY 1024
#define NX 1024
#define SX (1.0f / (1000.0f * 6.0f))   // DXI/6 (fluxes carry uniform x6)
#define SY (1.0f / (1000.0f * 6.0f))
#define JSTRIP 64
#define WARPS 4

typedef unsigned long long u64_t;

__device__ __forceinline__ u64_t pk2(float lo, float hi) {
    u64_t r; asm("mov.b64 %0, {%1, %2};" : "=l"(r) : "f"(lo), "f"(hi)); return r;
}
__device__ __forceinline__ void upk2(u64_t p, float& lo, float& hi) {
    asm("mov.b64 {%0, %1}, %2;" : "=f"(lo), "=f"(hi) : "l"(p));
}
__device__ __forceinline__ u64_t f2add(u64_t a, u64_t b) {
    u64_t r; asm("add.rn.f32x2 %0, %1, %2;" : "=l"(r) : "l"(a), "l"(b)); return r;
}
__device__ __forceinline__ u64_t f2mul(u64_t a, u64_t b) {
    u64_t r; asm("mul.rn.f32x2 %0, %1, %2;" : "=l"(r) : "l"(a), "l"(b)); return r;
}
__device__ __forceinline__ u64_t f2fma(u64_t a, u64_t b, u64_t c) {
    u64_t r; asm("fma.rn.f32x2 %0, %1, %2, %3;" : "=l"(r) : "l"(a), "l"(b), "l"(c)); return r;
}
__device__ __forceinline__ u64_t bcast2(float x) {
    unsigned uu = __float_as_uint(x);
    return ((u64_t)uu << 32) | (u64_t)uu;
}

// Packed WENO5 (Jiang-Shu), rescaled: B=12b, weights x10, polys x6 (1/6 folded into SX/SY).
__device__ __forceinline__ void weno5x2(u64_t qm2, u64_t qm1, u64_t q0,
                                        u64_t qp1, u64_t qp2,
                                        float& r0, float& r1) {
    const u64_t cm2 = bcast2(-2.f), cm4 = bcast2(-4.f), c3 = bcast2(3.f),
                c13 = bcast2(13.f), cm1 = bcast2(-1.f), c6 = bcast2(6.f),
                c2  = bcast2(2.f),  cm7 = bcast2(-7.f), c11 = bcast2(11.f),
                c5  = bcast2(5.f),  cE  = bcast2(1.2e-5f);   // 12*eps

    u64_t t0 = f2add(f2fma(qm1, cm2, q0), qm2);
    u64_t s0 = f2fma(qm1, cm4, f2fma(q0, c3, qm2));
    u64_t B0 = f2fma(f2mul(t0, c13), t0, f2mul(f2mul(s0, s0), c3));
    u64_t t1 = f2add(f2fma(q0, cm2, qp1), qm1);
    u64_t s1 = f2fma(qp1, cm1, qm1);
    u64_t B1 = f2fma(f2mul(t1, c13), t1, f2mul(f2mul(s1, s1), c3));
    u64_t t2 = f2add(f2fma(qp1, cm2, qp2), q0);
    u64_t s2 = f2fma(qp1, cm4, f2fma(q0, c3, qp2));
    u64_t B2 = f2fma(f2mul(t2, c13), t2, f2mul(f2mul(s2, s2), c3));

    u64_t d0 = f2add(B0, cE); d0 = f2mul(d0, d0);
    u64_t d1 = f2add(B1, cE); d1 = f2mul(d1, d1);
    u64_t d2 = f2add(B2, cE); d2 = f2mul(d2, d2);

    u64_t w0 = f2mul(d1, d2);
    u64_t w1 = f2mul(f2mul(d0, d2), c6);
    u64_t w2 = f2mul(f2mul(d0, d1), c3);

    u64_t P0 = f2fma(qm2, c2, f2fma(qm1, cm7, f2mul(q0, c11)));
    u64_t P1 = f2fma(qm1, cm1, f2fma(q0, c5, f2mul(qp1, c2)));
    u64_t P2 = f2fma(q0, c2, f2fma(qp1, c5, f2mul(qp2, cm1)));

    u64_t num = f2fma(w0, P0, f2fma(w1, P1, f2mul(w2, P2)));
    u64_t den = f2add(w0, f2add(w1, w2));
    float n0, n1, e0, e1;
    upk2(num, n0, n1); upk2(den, e0, e1);
    r0 = __fdividef(n0, e0);
    r1 = __fdividef(n1, e1);
}

// Upwind-select two 6-point stencils (a for lane-lo face, b for lane-hi face) and pack.
__device__ __forceinline__ void upwind_pack(const float a[6], const float b[6],
                                            bool ga, bool gb,
                                            u64_t& m2, u64_t& m1, u64_t& z0,
                                            u64_t& p1, u64_t& p2) {
    m2 = pk2(ga ? a[0] : a[5], gb ? b[0] : b[5]);
    m1 = pk2(ga ? a[1] : a[4], gb ? b[1] : b[4]);
    z0 = pk2(ga ? a[2] : a[3], gb ? b[2] : b[3]);
    p1 = pk2(ga ? a[3] : a[2], gb ? b[3] : b[2]);
    p2 = pk2(ga ? a[4] : a[1], gb ? b[4] : b[1]);
}

__global__ __launch_bounds__(32 * WARPS)
void adv3d_kernel(const float* __restrict__ h,
                  const float* __restrict__ u,
                  const float* __restrict__ v,
                  float* __restrict__ out) {
    const int k    = blockIdx.z;
    const int lane = threadIdx.x;
    const int w    = threadIdx.y;
    const int i0   = (blockIdx.x * WARPS + w) * 64;   // warp's x-chunk base
    const int ip   = i0 + 2 * lane;                   // this thread's 2 columns
    const int js   = blockIdx.y * JSTRIP;
    const int base = k * (NY * NX);
    const unsigned FULL = 0xffffffffu;

    if (k == 0 || k == NZ - 1) {                      // z boundary slabs: zeros
        for (int j = js; j < js + JSTRIP; j++)
            *(float2*)&out[base + j * NX + ip] = make_float2(0.f, 0.f);
        return;
    }

    __shared__ float sHalo[WARPS][JSTRIP];

    // ---- pre-phase: x-halo faces at x = i0-1, all 64 strip rows in one packed eval/lane ----
    {
        int ra = js + 2 * lane, rb = ra + 1;
        float a[6], b[6];
        #pragma unroll
        for (int m = 0; m < 6; m++) {
            int xi = min(max(i0 - 3 + m, 0), NX - 1);
            a[m] = __ldg(&h[base + ra * NX + xi]);
            b[m] = __ldg(&h[base + rb * NX + xi]);
        }
        int xh = max(i0 - 1, 0);
        float ua = __ldg(&u[base + ra * NX + xh]);
        float ub = __ldg(&u[base + rb * NX + xh]);
        u64_t m2, m1, z0, p1, p2;
        upwind_pack(a, b, ua >= 0.f, ub >= 0.f, m2, m1, z0, p1, p2);
        float f0, f1;
        weno5x2(m2, m1, z0, p1, p2, f0, f1);
        sHalo[w][2 * lane]     = f0 * ua;
        sHalo[w][2 * lane + 1] = f1 * ub;
    }
    __syncwarp();

    // ---- rolling warm-up: h rows js-3..js+2 (clamped) at own columns ----
    float2 r0, r1, r2, r3, r4, r5;
    {
        #define LOADROW(m) (*(const float2*)&h[base + min(max(js - 3 + (m), 0), NY - 1) * NX + ip])
        r0 = LOADROW(0); r1 = LOADROW(1); r2 = LOADROW(2);
        r3 = LOADROW(3); r4 = LOADROW(4); r5 = LOADROW(5);
        #undef LOADROW
    }

    // fn_prev: y-face at row js-1 (stencil rows js-3..js+2 = r0..r5)
    float2 fn_prev;
    {
        float2 vh = *(const float2*)&v[base + max(js - 1, 0) * NX + ip];
        float ay[6] = {r0.x, r1.x, r2.x, r3.x, r4.x, r5.x};
        float by[6] = {r0.y, r1.y, r2.y, r3.y, r4.y, r5.y};
        u64_t m2, m1, z0, p1, p2;
        upwind_pack(ay, by, vh.x >= 0.f, vh.y >= 0.f, m2, m1, z0, p1, p2);
        float f0, f1;
        weno5x2(m2, m1, z0, p1, p2, f0, f1);
        fn_prev = make_float2(f0 * vh.x, f1 * vh.y);
    }

    const bool left_edge  = (i0 == 0);
    const bool right_edge = (i0 == NX - 64);

    #pragma unroll 2
    for (int j = js; j < js + JSTRIP; j++) {
        // roll in row j+3 (clamped)
        float2 nr = *(const float2*)&h[base + min(j + 3, NY - 1) * NX + ip];
        r0 = r1; r1 = r2; r2 = r3; r3 = r4; r4 = r5; r5 = nr;
        // r0..r5 = rows j-2..j+3; center row j = r2
        float2 c = r2;

        // x-stencil neighbors via intra-warp shuffle
        float2 L, R1, R2;
        L.x  = __shfl_up_sync(FULL, c.x, 1);
        L.y  = __shfl_up_sync(FULL, c.y, 1);
        R1.x = __shfl_down_sync(FULL, c.x, 1);
        R1.y = __shfl_down_sync(FULL, c.y, 1);
        R2.x = __shfl_down_sync(FULL, c.x, 2);
        R2.y = __shfl_down_sync(FULL, c.y, 2);

        // cross-warp / domain-edge fixups (lanes 0, 30, 31 only)
        if (lane == 0) {
            if (left_edge) { L.x = c.x; L.y = c.x; }        // h[-2]=h[-1]=h[0]
            else            L = *(const float2*)&h[base + j * NX + (ip - 2)];
        }
        if (lane == 31) {
            if (right_edge) { R1.x = c.y; R1.y = c.y; R2 = R1; }  // clamp to h[NX-1]
            else {
                R1 = *(const float2*)&h[base + j * NX + (ip + 2)];
                R2 = *(const float2*)&h[base + j * NX + (ip + 4)];
            }
        } else if (lane == 30) {
            if (right_edge) { R2.x = R1.y; R2.y = R1.y; }
            else            R2 = *(const float2*)&h[base + j * NX + (ip + 4)];
        }

        // ---- x faces at (ip, ip+1): q[ip-2..ip+5] = L.x L.y c.x c.y R1.x R1.y R2.x R2.y ----
        float2 uv2 = *(const float2*)&u[base + j * NX + ip];
        float fx0, fx1;
        {
            float ax[6] = {L.x, L.y, c.x, c.y, R1.x, R1.y};
            float bx[6] = {L.y, c.x, c.y, R1.x, R1.y, R2.x};
            u64_t m2, m1, z0, p1, p2;
            upwind_pack(ax, bx, uv2.x >= 0.f, uv2.y >= 0.f, m2, m1, z0, p1, p2);
            weno5x2(m2, m1, z0, p1, p2, fx0, fx1);
            fx0 *= uv2.x; fx1 *= uv2.y;
        }
        float fxm = __shfl_up_sync(FULL, fx1, 1);    // face at ip-1 from left lane
        float halo = sHalo[w][j - js];
        if (lane == 0) fxm = halo;

        // ---- y faces at row j (stencil r0..r5, own columns) ----
        float2 vv2 = *(const float2*)&v[base + j * NX + ip];
        float fy0, fy1;
        {
            float ay[6] = {r0.x, r1.x, r2.x, r3.x, r4.x, r5.x};
            float by[6] = {r0.y, r1.y, r2.y, r3.y, r4.y, r5.y};
            u64_t m2, m1, z0, p1, p2;
            upwind_pack(ay, by, vv2.x >= 0.f, vv2.y >= 0.f, m2, m1, z0, p1, p2);
            weno5x2(m2, m1, z0, p1, p2, fy0, fy1);
            fy0 *= vv2.x; fy1 *= vv2.y;
        }

        float o0 = 0.f, o1 = 0.f;
        if (j >= 2 && j <= NY - 3) {
            if (ip >= 2 && ip <= NX - 3)
                o0 = -((fx0 - fxm) * SX + (fy0 - fn_prev.x) * SY);
            if (ip + 1 >= 2 && ip + 1 <= NX - 3)
                o1 = -((fx1 - fx0) * SX + (fy1 - fn_prev.y) * SY);
        }
        *(float2*)&out[base + j * NX + ip] = make_float2(o0, o1);
        fn_prev = make_float2(fy0, fy1);
    }
}

extern "C" void kernel_launch(void* const* d_in, const int* in_sizes, int n_in,
                              void* d_out, int out_size) {
    const float* h = (const float*)d_in[0];
    const float* u = (const float*)d_in[1];
    const float* v = (const float*)d_in[2];
    float* out = (float*)d_out;

    dim3 block(32, WARPS, 1);
    dim3 grid(NX / (64 * WARPS), NY / JSTRIP, NZ);
    adv3d_kernel<<<grid, block>>>(h, u, v, out);
}

// round 4
// speedup vs baseline: 1.9049x; 1.2018x over previous
#include <cuda_runtime.h>

#define NZ 32
#define NY 1024
#define NX 1024
#define SX (1.0f / (1000.0f * 6.0f))   // DXI/6 (fluxes carry uniform x6)
#define SY (1.0f / (1000.0f * 6.0f))
#define JSTRIP 64
#define WARPS 4

typedef unsigned long long u64_t;

__device__ __forceinline__ u64_t pk2(float lo, float hi) {
    u64_t r; asm("mov.b64 %0, {%1, %2};" : "=l"(r) : "f"(lo), "f"(hi)); return r;
}
__device__ __forceinline__ void upk2(u64_t p, float& lo, float& hi) {
    asm("mov.b64 {%0, %1}, %2;" : "=f"(lo), "=f"(hi) : "l"(p));
}
__device__ __forceinline__ u64_t f2add(u64_t a, u64_t b) {
    u64_t r; asm("add.rn.f32x2 %0, %1, %2;" : "=l"(r) : "l"(a), "l"(b)); return r;
}
__device__ __forceinline__ u64_t f2mul(u64_t a, u64_t b) {
    u64_t r; asm("mul.rn.f32x2 %0, %1, %2;" : "=l"(r) : "l"(a), "l"(b)); return r;
}
__device__ __forceinline__ u64_t f2fma(u64_t a, u64_t b, u64_t c) {
    u64_t r; asm("fma.rn.f32x2 %0, %1, %2, %3;" : "=l"(r) : "l"(a), "l"(b), "l"(c)); return r;
}
__device__ __forceinline__ u64_t bcast2(float x) {
    unsigned uu = __float_as_uint(x);
    return ((u64_t)uu << 32) | (u64_t)uu;
}

// Packed WENO5 (Jiang-Shu), rescaled: B=12b, weights x10, polys x6 (1/6 folded into SX/SY).
__device__ __forceinline__ void weno5x2(u64_t qm2, u64_t qm1, u64_t q0,
                                        u64_t qp1, u64_t qp2,
                                        float& r0, float& r1) {
    const u64_t cm2 = bcast2(-2.f), cm4 = bcast2(-4.f), c3 = bcast2(3.f),
                c13 = bcast2(13.f), cm1 = bcast2(-1.f), c6 = bcast2(6.f),
                c2  = bcast2(2.f),  cm7 = bcast2(-7.f), c11 = bcast2(11.f),
                c5  = bcast2(5.f),  cE  = bcast2(1.2e-5f);   // 12*eps

    u64_t t0 = f2add(f2fma(qm1, cm2, q0), qm2);
    u64_t s0 = f2fma(qm1, cm4, f2fma(q0, c3, qm2));
    u64_t B0 = f2fma(f2mul(t0, c13), t0, f2mul(f2mul(s0, s0), c3));
    u64_t t1 = f2add(f2fma(q0, cm2, qp1), qm1);
    u64_t s1 = f2fma(qp1, cm1, qm1);
    u64_t B1 = f2fma(f2mul(t1, c13), t1, f2mul(f2mul(s1, s1), c3));
    u64_t t2 = f2add(f2fma(qp1, cm2, qp2), q0);
    u64_t s2 = f2fma(qp1, cm4, f2fma(q0, c3, qp2));
    u64_t B2 = f2fma(f2mul(t2, c13), t2, f2mul(f2mul(s2, s2), c3));

    u64_t d0 = f2add(B0, cE); d0 = f2mul(d0, d0);
    u64_t d1 = f2add(B1, cE); d1 = f2mul(d1, d1);
    u64_t d2 = f2add(B2, cE); d2 = f2mul(d2, d2);

    u64_t w0 = f2mul(d1, d2);
    u64_t w1 = f2mul(f2mul(d0, d2), c6);
    u64_t w2 = f2mul(f2mul(d0, d1), c3);

    u64_t P0 = f2fma(qm2, c2, f2fma(qm1, cm7, f2mul(q0, c11)));
    u64_t P1 = f2fma(qm1, cm1, f2fma(q0, c5, f2mul(qp1, c2)));
    u64_t P2 = f2fma(q0, c2, f2fma(qp1, c5, f2mul(qp2, cm1)));

    u64_t num = f2fma(w0, P0, f2fma(w1, P1, f2mul(w2, P2)));
    u64_t den = f2add(w0, f2add(w1, w2));
    float n0, n1, e0, e1;
    upk2(num, n0, n1); upk2(den, e0, e1);
    r0 = __fdividef(n0, e0);
    r1 = __fdividef(n1, e1);
}

__device__ __forceinline__ void upwind_pack(const float a[6], const float b[6],
                                            bool ga, bool gb,
                                            u64_t& m2, u64_t& m1, u64_t& z0,
                                            u64_t& p1, u64_t& p2) {
    m2 = pk2(ga ? a[0] : a[5], gb ? b[0] : b[5]);
    m1 = pk2(ga ? a[1] : a[4], gb ? b[1] : b[4]);
    z0 = pk2(ga ? a[2] : a[3], gb ? b[2] : b[3]);
    p1 = pk2(ga ? a[3] : a[2], gb ? b[3] : b[2]);
    p2 = pk2(ga ? a[4] : a[1], gb ? b[4] : b[1]);
}

__global__ __launch_bounds__(32 * WARPS)
void adv3d_kernel(const float* __restrict__ h,
                  const float* __restrict__ u,
                  const float* __restrict__ v,
                  float* __restrict__ out) {
    const int k    = blockIdx.z;
    const int lane = threadIdx.x;
    const int w    = threadIdx.y;
    const int i0   = (blockIdx.x * WARPS + w) * 64;
    const int ip   = i0 + 2 * lane;
    const int js   = blockIdx.y * JSTRIP;
    const int base = k * (NY * NX);
    const unsigned FULL = 0xffffffffu;

    if (k == 0 || k == NZ - 1) {                 // z boundary slabs: zeros
        for (int j = js; j < js + JSTRIP; j++)
            *(float2*)&out[base + j * NX + ip] = make_float2(0.f, 0.f);
        return;
    }

    __shared__ float sHalo[WARPS][JSTRIP];

    const bool left_edge  = (i0 == 0);
    const bool right_edge = (i0 == NX - 64);

    // ---- pre-phase: x-halo faces at x = i0-1 for all 64 strip rows (one packed eval/lane) ----
    {
        int ra = js + 2 * lane, rb = ra + 1;
        float a[6], b[6];
        #pragma unroll
        for (int m = 0; m < 6; m++) {
            int xi = min(max(i0 - 3 + m, 0), NX - 1);
            a[m] = __ldg(&h[base + ra * NX + xi]);
            b[m] = __ldg(&h[base + rb * NX + xi]);
        }
        int xh = max(i0 - 1, 0);
        float ua = __ldg(&u[base + ra * NX + xh]);
        float ub = __ldg(&u[base + rb * NX + xh]);
        u64_t m2, m1, z0, p1, p2;
        upwind_pack(a, b, ua >= 0.f, ub >= 0.f, m2, m1, z0, p1, p2);
        float f0, f1;
        weno5x2(m2, m1, z0, p1, p2, f0, f1);
        sHalo[w][2 * lane]     = f0 * ua;
        sHalo[w][2 * lane + 1] = f1 * ub;
    }
    __syncwarp();

    // ---- halo-column register pipeline setup ----
    // lane 0  -> cols i0-2..i0-1 (its L)       [skip if left edge]
    // lane 30 -> cols i0+64..65  (its R2)      [skip if right edge]
    // lane 31 -> cols i0+66..67  (its R2; R1 comes from lane30's reg via shfl)
    const int haloCol  = (lane == 0) ? max(i0 - 2, 0) : ((lane == 30) ? i0 + 64 : i0 + 66);
    const bool needHalo = (lane == 0) ? !left_edge
                         : ((lane == 30 || lane == 31) ? !right_edge : false);
    const int haloColC = min(haloCol, NX - 2);   // safe address even when unused

    // ---- rolling h rows: r0..r5 = rows js-3..js+2, rp = row js+3 (prefetched) ----
    float2 r0, r1, r2, r3, r4, r5, rp;
    {
        #define LOADROW(m) (*(const float2*)&h[base + min(max(js - 3 + (m), 0), NY - 1) * NX + ip])
        r0 = LOADROW(0); r1 = LOADROW(1); r2 = LOADROW(2);
        r3 = LOADROW(3); r4 = LOADROW(4); r5 = LOADROW(5);
        rp = LOADROW(6);
        #undef LOADROW
    }
    // halo pipeline: a0,a1,a2 = halo at rows js, js+1, js+2
    float2 a0, a1, a2;
    if (needHalo) {
        a0 = *(const float2*)&h[base + (js    ) * NX + haloColC];
        a1 = *(const float2*)&h[base + (js + 1) * NX + haloColC];
        a2 = *(const float2*)&h[base + (js + 2) * NX + haloColC];
    } else { a0 = a1 = a2 = make_float2(0.f, 0.f); }
    // u/v prefetch (row js)
    float2 uv = *(const float2*)&u[base + js * NX + ip];
    float2 vv = *(const float2*)&v[base + js * NX + ip];

    // fn_prev: y-face at row js-1 (stencil rows js-3..js+2 = r0..r5)
    float2 fn_prev;
    {
        float2 vh = *(const float2*)&v[base + max(js - 1, 0) * NX + ip];
        float ay[6] = {r0.x, r1.x, r2.x, r3.x, r4.x, r5.x};
        float by[6] = {r0.y, r1.y, r2.y, r3.y, r4.y, r5.y};
        u64_t m2, m1, z0, p1, p2;
        upwind_pack(ay, by, vh.x >= 0.f, vh.y >= 0.f, m2, m1, z0, p1, p2);
        float f0, f1;
        weno5x2(m2, m1, z0, p1, p2, f0, f1);
        fn_prev = make_float2(f0 * vh.x, f1 * vh.y);
    }

    #pragma unroll 4
    for (int j = js; j < js + JSTRIP; j++) {
        // ---- issue ALL prefetches first (consumed next iterations) ----
        float2 rpN = *(const float2*)&h[base + min(j + 4, NY - 1) * NX + ip];   // row j+4
        float2 aN = make_float2(0.f, 0.f);
        if (needHalo)
            aN = *(const float2*)&h[base + min(j + 3, NY - 1) * NX + haloColC]; // halo row j+3
        int jn = min(j + 1, NY - 1);
        float2 uvN = *(const float2*)&u[base + jn * NX + ip];                   // row j+1
        float2 vvN = *(const float2*)&v[base + jn * NX + ip];

        // ---- shift rows: r0..r5 = rows j-2..j+3 (rp was prefetched last iter) ----
        r0 = r1; r1 = r2; r2 = r3; r3 = r4; r4 = r5; r5 = rp;
        float2 c = r2;                                   // center row j

        // x-stencil neighbors via intra-warp shuffle
        float2 L, R1, R2;
        L.x  = __shfl_up_sync(FULL, c.x, 1);
        L.y  = __shfl_up_sync(FULL, c.y, 1);
        R1.x = __shfl_down_sync(FULL, c.x, 1);
        R1.y = __shfl_down_sync(FULL, c.y, 1);
        R2.x = __shfl_down_sync(FULL, c.x, 2);
        R2.y = __shfl_down_sync(FULL, c.y, 2);

        // lane31's R1 (cols i0+64..65) = lane30's halo reg, via shuffle (convergent)
        float h30x = __shfl_sync(FULL, a0.x, 30);
        float h30y = __shfl_sync(FULL, a0.y, 30);

        // edge/cross-warp fixups from the halo pipeline (register-only)
        if (lane == 0)
            L = left_edge ? make_float2(c.x, c.x) : a0;
        if (lane == 31) {
            R1 = right_edge ? make_float2(c.y, c.y) : make_float2(h30x, h30y);
            R2 = right_edge ? make_float2(c.y, c.y) : a0;
        } else if (lane == 30) {
            R2 = right_edge ? make_float2(R1.y, R1.y) : a0;
        }

        // ---- x faces at (ip, ip+1) ----
        float fx0, fx1;
        {
            float ax[6] = {L.x, L.y, c.x, c.y, R1.x, R1.y};
            float bx[6] = {L.y, c.x, c.y, R1.x, R1.y, R2.x};
            u64_t m2, m1, z0, p1, p2;
            upwind_pack(ax, bx, uv.x >= 0.f, uv.y >= 0.f, m2, m1, z0, p1, p2);
            weno5x2(m2, m1, z0, p1, p2, fx0, fx1);
            fx0 *= uv.x; fx1 *= uv.y;
        }
        float fxm = __shfl_up_sync(FULL, fx1, 1);        // face at ip-1 from left lane
        float halo = sHalo[w][j - js];
        if (lane == 0) fxm = halo;

        // ---- y faces at row j (rows j-2..j+3 = r0..r5) ----
        float fy0, fy1;
        {
            float ay[6] = {r0.x, r1.x, r2.x, r3.x, r4.x, r5.x};
            float by[6] = {r0.y, r1.y, r2.y, r3.y, r4.y, r5.y};
            u64_t m2, m1, z0, p1, p2;
            upwind_pack(ay, by, vv.x >= 0.f, vv.y >= 0.f, m2, m1, z0, p1, p2);
            weno5x2(m2, m1, z0, p1, p2, fy0, fy1);
            fy0 *= vv.x; fy1 *= vv.y;
        }

        float o0 = 0.f, o1 = 0.f;
        if (j >= 2 && j <= NY - 3) {
            if (ip >= 2 && ip <= NX - 3)
                o0 = -((fx0 - fxm) * SX + (fy0 - fn_prev.x) * SY);
            if (ip + 1 >= 2 && ip + 1 <= NX - 3)
                o1 = -((fx1 - fx0) * SX + (fy1 - fn_prev.y) * SY);
        }
        *(float2*)&out[base + j * NX + ip] = make_float2(o0, o1);

        // ---- rotate pipelines ----
        fn_prev = make_float2(fy0, fy1);
        rp = rpN;
        a0 = a1; a1 = a2; a2 = aN;
        uv = uvN; vv = vvN;
    }
}

extern "C" void kernel_launch(void* const* d_in, const int* in_sizes, int n_in,
                              void* d_out, int out_size) {
    const float* h = (const float*)d_in[0];
    const float* u = (const float*)d_in[1];
    const float* v = (const float*)d_in[2];
    float* out = (float*)d_out;

    dim3 block(32, WARPS, 1);
    dim3 grid(NX / (64 * WARPS), NY / JSTRIP, NZ);
    adv3d_kernel<<<grid, block>>>(h, u, v, out);
}